// round 12
// baseline (speedup 1.0000x reference)
#include <cuda_runtime.h>
#include <math.h>

#define BATCH    16
#define NBOX     120000
#define NCH      22
#define NMS_MAX  400
#define NUM_PRED 10
#define BINS     1024
#define CAP0     4096
#define THR0     0.984375f
#define SORTW    1024
#define MASKW    7
#define NW16     28            // u16 words per row (25 used, 3 zero) = 7 u64
#define NWPAIR   14
#define NF4      (NBOX * NCH / 4)   // 660000 float4 per batch
#define XBLK     256                // extract blocks per batch

// ---------------- scratch ----------------------------------------------------
__device__ int                g_cc[BATCH];     // zero-init; extract last block resets
__device__ int                g_done[BATCH];
__device__ int                g_m[BATCH];
__device__ int                g_fast[BATCH];
__device__ unsigned long long g_cand0[BATCH][CAP0];
__device__ float              g_sc[BATCH][NMS_MAX];
__device__ int                g_sidx[BATCH][NMS_MAX];
__device__ __align__(16) float g_bx[BATCH][NMS_MAX * 4];
__device__ __align__(8) unsigned short g_ov16[BATCH][NMS_MAX * NW16];

__device__ __forceinline__ unsigned int fkey(float f) {
    unsigned int u = __float_as_uint(f);
    return (u & 0x80000000u) ? ~u : (u | 0x80000000u);
}
__device__ __forceinline__ float fkey_inv(unsigned int k) {
    unsigned int u = (k & 0x80000000u) ? (k & 0x7fffffffu) : ~k;
    return __uint_as_float(u);
}
__device__ __forceinline__ int binf(float s) {     // fine bins over [THR0,1)
    int b = (int)((s - THR0) * 65536.0f);
    if (b < 0) b = 0;
    if (b > BINS - 1) b = BINS - 1;
    return b;
}
__device__ __forceinline__ int binc(float s) {     // coarse bins (fallback)
    int b = (int)(s * (float)BINS);
    if (b < 0) b = 0;
    if (b > BINS - 1) b = BINS - 1;
    return b;
}
__device__ __forceinline__ unsigned long long below_mask(int x) {
    return (x == 0) ? 0ULL : ((~0ULL) >> (64 - x));
}
__device__ __forceinline__ unsigned long long mkkey(float s, unsigned int idx) {
    return ((unsigned long long)fkey(s) << 32) | (unsigned long long)(~idx);
}

// ============ L1: fully-coalesced streaming collect + fused flags ============
// Lane f reads float4 #f of the batch; scores sit at f%11==0 (.y) and ==5 (.w).
__global__ void k_extract(const float* __restrict__ y) {
    int b = blockIdx.y;
    const float4* base4 = (const float4*)(y + (size_t)b * NBOX * NCH);
    int stride = gridDim.x * blockDim.x;
#pragma unroll 4
    for (int f = blockIdx.x * blockDim.x + threadIdx.x; f < NF4; f += stride) {
        float4 v = __ldcs(&base4[f]);
        int tile = f / 11;
        int pos  = f - tile * 11;
        float s = 0.0f;
        unsigned int idx = 0;
        if (pos == 0)      { s = v.y; idx = (unsigned int)(2 * tile); }
        else if (pos == 5) { s = v.w; idx = (unsigned int)(2 * tile + 1); }
        if (s >= THR0) {
            int p = atomicAdd(&g_cc[b], 1);
            if (p < CAP0) g_cand0[b][p] = mkkey(s, idx);
        }
    }

    __syncthreads();
    if (threadIdx.x == 0) {
        __threadfence();
        int old = atomicAdd(&g_done[b], 1);
        if (old == gridDim.x - 1) {
            __threadfence();
            int cc = g_cc[b];
            g_m[b]    = (cc < CAP0) ? cc : CAP0;
            g_fast[b] = (cc >= NMS_MAX && cc <= CAP0) ? 1 : 0;
            g_cc[b]   = 0;
            g_done[b] = 0;
        }
    }
}

// ============ L2: candidate hist + cutoff + filter + sort + decode ===========
__global__ __launch_bounds__(1024, 1)
void k_sortdecode(const float* __restrict__ y) {
    __shared__ __align__(16) unsigned long long cand[SORTW];
    __shared__ unsigned int hist[BINS];
    __shared__ int s_m, s_cut;
    int b = blockIdx.x, tid = threadIdx.x, lane = tid & 31;
    int fast = g_fast[b];
    int cc = g_m[b];

    if (tid == 0) s_m = 0;
    cand[tid] = 0ULL;
    hist[tid] = 0u;
    __syncthreads();

    if (fast) {
        for (int i = tid; i < cc; i += 1024) {
            float s = fkey_inv((unsigned int)(g_cand0[b][i] >> 32));
            atomicAdd(&hist[binf(s)], 1u);
        }
    } else {
        const float* base = y + (size_t)b * NBOX * NCH + 1;
        for (int i = tid; i < NBOX; i += 1024) {
            float s = base[(size_t)i * NCH];
            atomicAdd(&hist[binc(s)], 1u);
        }
    }
    __syncthreads();

    if (tid < 32) {
        int cum = 0, cut = 0;
        for (int base = BINS - 32; base >= 0; base -= 32) {
            int p = (int)hist[base + 31 - lane];
#pragma unroll
            for (int o = 1; o < 32; o <<= 1) {
                int t = __shfl_up_sync(0xffffffffu, p, o);
                if (lane >= o) p += t;
            }
            unsigned ball = __ballot_sync(0xffffffffu, cum + p >= NMS_MAX);
            if (ball) { cut = base + 31 - (__ffs(ball) - 1); break; }
            cum += __shfl_sync(0xffffffffu, p, 31);
        }
        if (lane == 0) s_cut = cut;
    }
    __syncthreads();
    int cut = s_cut;

    if (fast) {
        for (int i = tid; i < cc; i += 1024) {
            unsigned long long k = g_cand0[b][i];
            float s = fkey_inv((unsigned int)(k >> 32));
            if (binf(s) >= cut) {
                int p = atomicAdd(&s_m, 1);
                if (p < SORTW) cand[p] = k;
            }
        }
    } else {
        const float* base = y + (size_t)b * NBOX * NCH + 1;
        for (int i = tid; i < NBOX; i += 1024) {
            float s = base[(size_t)i * NCH];
            if (binc(s) >= cut) {
                int p = atomicAdd(&s_m, 1);
                if (p < SORTW) cand[p] = mkkey(s, (unsigned int)i);
            }
        }
    }
    __syncthreads();
    int m = s_m; if (m > SORTW) m = SORTW;
    int n = 512; while (n < m) n <<= 1;

    unsigned long long v = (tid < n) ? cand[tid] : 0ULL;

    for (int k = 2; k <= n; k <<= 1) {
        for (int j = k >> 1; j > 0; j >>= 1) {
            bool keep_max = (((tid & j) == 0) == ((tid & k) == 0));
            unsigned long long o;
            if (j < 32) {
                o = __shfl_xor_sync(0xffffffffu, v, j);
            } else {
                cand[tid] = v;
                __syncthreads();
                o = cand[tid ^ j];
                __syncthreads();
            }
            unsigned long long mx = (v > o) ? v : o;
            unsigned long long mn = (v > o) ? o : v;
            v = keep_max ? mx : mn;
        }
    }

    if (tid < NMS_MAX) {
        float s = fkey_inv((unsigned int)(v >> 32));
        unsigned int idx = ~(unsigned int)(v & 0xffffffffu);
        if (idx >= NBOX) idx = 0;
        g_sc[b][tid] = s;
        g_sidx[b][tid] = (int)idx;
        const float* r = y + ((size_t)b * NBOX + idx) * NCH;
        float l0 = r[2], l1 = r[3], l2 = r[4], l3 = r[5];
        float dcx = r[14], dcy = r[15], dw = r[16], dh = r[17];
        float v0 = r[18], v1 = r[19], v2 = r[20], v3 = r[21];
        float cx = l0 * v0 * dw + dcx;
        float cy = l1 * v1 * dh + dcy;
        float w  = expf(l2 * v2) * dw;
        float h  = expf(l3 * v3) * dh;
        g_bx[b][tid*4+0] = (cx - w * 0.5f) * 384.0f;
        g_bx[b][tid*4+1] = (cy - h * 0.5f) * 384.0f;
        g_bx[b][tid*4+2] = (cx + w * 0.5f) * 384.0f;
        g_bx[b][tid*4+3] = (cy + h * 0.5f) * 384.0f;
    }
}

// ============ L3: IoU masks — 2 words per thread, broadcast j-loop ===========
#define ROWS_HALF 200
__global__ __launch_bounds__(256, 6) void k_iou() {
    __shared__ __align__(16) float4 bxs4[NMS_MAX];
    int wp = blockIdx.x, half = blockIdx.y, b = blockIdx.z;
    int tid = threadIdx.x;
    const float4* src = (const float4*)g_bx[b];
    for (int i = tid; i < NMS_MAX; i += 256) bxs4[i] = src[i];
    __syncthreads();

    if (tid >= ROWS_HALF) return;
    int i = half * ROWS_HALF + tid;
    float4 A = bxs4[i];
    float areai = (A.z - A.x) * (A.w - A.y);

#pragma unroll
    for (int ww = 0; ww < 2; ++ww) {
        int w = wp + ww * NWPAIR;
        if (w >= 25) {
            g_ov16[b][i * NW16 + w] = 0;
            continue;
        }
        int j0 = w * 16;
        unsigned int m = 0;
#pragma unroll 4
        for (int jj = 0; jj < 16; ++jj) {
            float4 B = bxs4[j0 + jj];
            float lt0 = fmaxf(A.x, B.x), lt1 = fmaxf(A.y, B.y);
            float rb0 = fminf(A.z, B.z), rb1 = fminf(A.w, B.w);
            float w0 = fmaxf(rb0 - lt0, 0.0f);
            float w1 = fmaxf(rb1 - lt1, 0.0f);
            float inter = w0 * w1;
            float areaj = (B.z - B.x) * (B.w - B.y);
            float uni = areai + areaj - inter;
            if (inter / fmaxf(uni, 1e-8f) > 0.45f) m |= (1u << jj);
        }
        g_ov16[b][i * NW16 + w] = (unsigned short)m;
    }
}

// ============ L4: early-exit warp greedy + selection + output ================
__global__ __launch_bounds__(512, 1)
void k_greedy(const float* __restrict__ y, float* __restrict__ out) {
    __shared__ unsigned long long keepw[MASKW];
    __shared__ int sel[NUM_PRED], selk[NUM_PRED];
    __shared__ int pp[MASKW + 1];

    int b = blockIdx.x, tid = threadIdx.x;
    if (tid < MASKW) keepw[tid] = 0ULL;
    __syncthreads();

    if (tid < 32) {
        int t = tid;
        const unsigned long long* ov = (const unsigned long long*)g_ov16[b];
        unsigned long long kw[MASKW] = {0, 0, 0, 0, 0, 0, 0};
        int cnt = 0;
#pragma unroll
        for (int blk = 0; blk < MASKW; ++blk) {
            int ilo = blk * 64 + t;
            int ihi = ilo + 32;
            unsigned long long rlo[MASKW], rhi[MASKW];
            float slo = 0.0f, shi = 0.0f;
#pragma unroll
            for (int w = 0; w < MASKW; ++w) { rlo[w] = 0ULL; rhi[w] = 0ULL; }
            if (ilo < NMS_MAX) {
#pragma unroll
                for (int w = 0; w < MASKW; ++w) rlo[w] = ov[ilo * MASKW + w];
                slo = g_sc[b][ilo];
            }
            if (ihi < NMS_MAX) {
#pragma unroll
                for (int w = 0; w < MASKW; ++w) rhi[w] = ov[ihi * MASKW + w];
                shi = g_sc[b][ihi];
            }
            unsigned long long hlo = 0ULL, hhi = 0ULL;
#pragma unroll
            for (int w = 0; w < MASKW; ++w) {
                hlo |= rlo[w] & kw[w];
                hhi |= rhi[w] & kw[w];
            }
            bool oklo = (ilo < NMS_MAX) && (slo > 0.01f) && (hlo == 0ULL);
            bool okhi = (ihi < NMS_MAX) && (shi > 0.01f) && (hhi == 0ULL);
            unsigned blo = __ballot_sync(0xffffffffu, oklo);
            unsigned bhi = __ballot_sync(0xffffffffu, okhi);
            unsigned long long K = (unsigned long long)blo |
                                   ((unsigned long long)bhi << 32);
            unsigned long long Mlo = rlo[blk] & below_mask(t);
            unsigned long long Mhi = rhi[blk] & below_mask(t + 32);
            while (true) {
                bool badlo = ((K >> t) & 1ULL) && (Mlo & K);
                bool badhi = ((K >> (t + 32)) & 1ULL) && (Mhi & K);
                unsigned bl = __ballot_sync(0xffffffffu, badlo);
                unsigned bh = __ballot_sync(0xffffffffu, badhi);
                unsigned long long bad = (unsigned long long)bl |
                                         ((unsigned long long)bh << 32);
                if (!bad) break;
                K &= ~(bad & (0ULL - bad));
            }
            kw[blk] = K;
            cnt += __popcll(K);                 // uniform across lanes
            if (cnt >= NUM_PRED) break;          // exact: fillers unreachable
        }
        if (t < MASKW) keepw[t] = kw[t];
        if (t == 0) {
            pp[0] = 0;
#pragma unroll
            for (int w = 0; w < MASKW; ++w) pp[w + 1] = pp[w] + __popcll(kw[w]);
        }
    }
    __syncthreads();

    if (tid < NMS_MAX) {
        int w = tid >> 6, bit = tid & 63;
        unsigned long long below = keepw[w] & below_mask(bit);
        int keptBefore = pp[w] + __popcll(below);
        bool kept = (keepw[w] >> bit) & 1ULL;
        int K = pp[MASKW];
        if (kept) {
            if (keptBefore < NUM_PRED) { sel[keptBefore] = tid; selk[keptBefore] = 1; }
        } else {
            int r = K + (tid - keptBefore);
            if (r < NUM_PRED) { sel[r] = tid; selk[r] = 0; }
        }
    }
    __syncthreads();

    if (tid < NUM_PRED) {
        int i = sel[tid];
        float* o = out + ((size_t)b * NUM_PRED + tid) * 13;
        o[0] = selk[tid] ? g_sc[b][i] : -1.0f;
        o[1] = g_bx[b][i*4+0]; o[2] = g_bx[b][i*4+1];
        o[3] = g_bx[b][i*4+2]; o[4] = g_bx[b][i*4+3];
        const float* r = y + ((size_t)b * NBOX + g_sidx[b][i]) * NCH;
        float dcx = r[14], dcy = r[15], dw = r[16], dh = r[17];
        float v0 = r[18], v1 = r[19];
        float dqx[4] = {dcx - dw*0.5f, dcx + dw*0.5f, dcx + dw*0.5f, dcx - dw*0.5f};
        float dqy[4] = {dcy - dh*0.5f, dcy - dh*0.5f, dcy + dh*0.5f, dcy + dh*0.5f};
#pragma unroll
        for (int k = 0; k < 4; ++k) {
            float qx = dqx[k] + r[6 + 2*k] * v0 * dw;
            float qy = dqy[k] + r[7 + 2*k] * v1 * dh;
            o[5 + 2*k]     = qx * 384.0f;
            o[5 + 2*k + 1] = qy * 384.0f;
        }
    }
}

// ---------------- launch ---------------------------------------------------
extern "C" void kernel_launch(void* const* d_in, const int* in_sizes, int n_in,
                              void* d_out, int out_size) {
    const float* y = (const float*)d_in[0];
    float* out = (float*)d_out;
    k_extract<<<dim3(XBLK, BATCH), 256>>>(y);
    k_sortdecode<<<BATCH, 1024>>>(y);
    k_iou<<<dim3(NWPAIR, 2, BATCH), 256>>>();
    k_greedy<<<BATCH, 512>>>(y, out);
}

// round 13
// speedup vs baseline: 1.0598x; 1.0598x over previous
#include <cuda_runtime.h>
#include <math.h>

#define BATCH    16
#define NBOX     120000
#define NCH      22
#define NMS_MAX  400
#define NUM_PRED 10
#define BINS     1024
#define HBLK     64
#define CAP0     4096
#define THR0     0.984375f
#define SORTW    1024
#define MASKW    7
#define NW16     28            // u16 words per row (25 used, 3 zero) = 7 u64
#define NWPAIR   14
#define NTILE    (NBOX / 2)

// ---------------- scratch ----------------------------------------------------
__device__ int                g_cc[BATCH];     // zero-init; extract last block resets
__device__ int                g_done[BATCH];
__device__ int                g_m[BATCH];
__device__ int                g_fast[BATCH];
__device__ unsigned long long g_cand0[BATCH][CAP0];
__device__ float              g_sc[BATCH][NMS_MAX];
__device__ int                g_sidx[BATCH][NMS_MAX];
__device__ __align__(16) float g_bx[BATCH][NMS_MAX * 4];
__device__ __align__(8) unsigned short g_ov16[BATCH][NMS_MAX * NW16];

__device__ __forceinline__ unsigned int fkey(float f) {
    unsigned int u = __float_as_uint(f);
    return (u & 0x80000000u) ? ~u : (u | 0x80000000u);
}
__device__ __forceinline__ float fkey_inv(unsigned int k) {
    unsigned int u = (k & 0x80000000u) ? (k & 0x7fffffffu) : ~k;
    return __uint_as_float(u);
}
__device__ __forceinline__ int binf(float s) {     // fine bins over [THR0,1)
    int b = (int)((s - THR0) * 65536.0f);
    if (b < 0) b = 0;
    if (b > BINS - 1) b = BINS - 1;
    return b;
}
__device__ __forceinline__ int binc(float s) {     // coarse bins (fallback)
    int b = (int)(s * (float)BINS);
    if (b < 0) b = 0;
    if (b > BINS - 1) b = BINS - 1;
    return b;
}
__device__ __forceinline__ unsigned long long below_mask(int x) {
    return (x == 0) ? 0ULL : ((~0ULL) >> (64 - x));
}
__device__ __forceinline__ unsigned long long mkkey(float s, unsigned int idx) {
    return ((unsigned long long)fkey(s) << 32) | (unsigned long long)(~idx);
}

// ============ L1: strided threshold collect (min LDG count) + fused flags ====
__global__ void k_extract(const float* __restrict__ y) {
    int b = blockIdx.y;
    const float4* base4 = (const float4*)(y + (size_t)b * NBOX * NCH);
    int stride = gridDim.x * blockDim.x;
    int t = blockIdx.x * blockDim.x + threadIdx.x;
    for (; t + stride < NTILE; t += 2 * stride) {
        int t2 = t + stride;
        float4 a0 = __ldcs(&base4[11 * t]);
        float4 c0 = __ldcs(&base4[11 * t + 5]);
        float4 a1 = __ldcs(&base4[11 * t2]);
        float4 c1 = __ldcs(&base4[11 * t2 + 5]);
        float s00 = a0.y, s01 = c0.w, s10 = a1.y, s11 = c1.w;
        if (s00 >= THR0) {
            int p = atomicAdd(&g_cc[b], 1);
            if (p < CAP0) g_cand0[b][p] = mkkey(s00, (unsigned int)(2 * t));
        }
        if (s01 >= THR0) {
            int p = atomicAdd(&g_cc[b], 1);
            if (p < CAP0) g_cand0[b][p] = mkkey(s01, (unsigned int)(2 * t + 1));
        }
        if (s10 >= THR0) {
            int p = atomicAdd(&g_cc[b], 1);
            if (p < CAP0) g_cand0[b][p] = mkkey(s10, (unsigned int)(2 * t2));
        }
        if (s11 >= THR0) {
            int p = atomicAdd(&g_cc[b], 1);
            if (p < CAP0) g_cand0[b][p] = mkkey(s11, (unsigned int)(2 * t2 + 1));
        }
    }
    if (t < NTILE) {
        float4 a = __ldcs(&base4[11 * t]);
        float4 c = __ldcs(&base4[11 * t + 5]);
        float s0 = a.y, s1 = c.w;
        if (s0 >= THR0) {
            int p = atomicAdd(&g_cc[b], 1);
            if (p < CAP0) g_cand0[b][p] = mkkey(s0, (unsigned int)(2 * t));
        }
        if (s1 >= THR0) {
            int p = atomicAdd(&g_cc[b], 1);
            if (p < CAP0) g_cand0[b][p] = mkkey(s1, (unsigned int)(2 * t + 1));
        }
    }

    // ---- fused flags: last block of this batch publishes m/fast, resets ----
    __syncthreads();
    if (threadIdx.x == 0) {
        __threadfence();
        int old = atomicAdd(&g_done[b], 1);
        if (old == gridDim.x - 1) {
            __threadfence();
            int cc = g_cc[b];
            g_m[b]    = (cc < CAP0) ? cc : CAP0;
            g_fast[b] = (cc >= NMS_MAX && cc <= CAP0) ? 1 : 0;
            g_cc[b]   = 0;
            g_done[b] = 0;
        }
    }
}

// ============ L2: candidate hist + cutoff + filter + sort + decode ===========
__global__ __launch_bounds__(1024, 1)
void k_sortdecode(const float* __restrict__ y) {
    __shared__ __align__(16) unsigned long long cand[SORTW];
    __shared__ unsigned int hist[BINS];
    __shared__ int s_m, s_cut;
    int b = blockIdx.x, tid = threadIdx.x, lane = tid & 31;
    int fast = g_fast[b];
    int cc = g_m[b];

    if (tid == 0) s_m = 0;
    cand[tid] = 0ULL;
    hist[tid] = 0u;
    __syncthreads();

    if (fast) {
        for (int i = tid; i < cc; i += 1024) {
            float s = fkey_inv((unsigned int)(g_cand0[b][i] >> 32));
            atomicAdd(&hist[binf(s)], 1u);
        }
    } else {
        const float* base = y + (size_t)b * NBOX * NCH + 1;
        for (int i = tid; i < NBOX; i += 1024) {
            float s = base[(size_t)i * NCH];
            atomicAdd(&hist[binc(s)], 1u);
        }
    }
    __syncthreads();

    if (tid < 32) {
        int cum = 0, cut = 0;
        for (int base = BINS - 32; base >= 0; base -= 32) {
            int p = (int)hist[base + 31 - lane];
#pragma unroll
            for (int o = 1; o < 32; o <<= 1) {
                int t = __shfl_up_sync(0xffffffffu, p, o);
                if (lane >= o) p += t;
            }
            unsigned ball = __ballot_sync(0xffffffffu, cum + p >= NMS_MAX);
            if (ball) { cut = base + 31 - (__ffs(ball) - 1); break; }
            cum += __shfl_sync(0xffffffffu, p, 31);
        }
        if (lane == 0) s_cut = cut;
    }
    __syncthreads();
    int cut = s_cut;

    if (fast) {
        for (int i = tid; i < cc; i += 1024) {
            unsigned long long k = g_cand0[b][i];
            float s = fkey_inv((unsigned int)(k >> 32));
            if (binf(s) >= cut) {
                int p = atomicAdd(&s_m, 1);
                if (p < SORTW) cand[p] = k;
            }
        }
    } else {
        const float* base = y + (size_t)b * NBOX * NCH + 1;
        for (int i = tid; i < NBOX; i += 1024) {
            float s = base[(size_t)i * NCH];
            if (binc(s) >= cut) {
                int p = atomicAdd(&s_m, 1);
                if (p < SORTW) cand[p] = mkkey(s, (unsigned int)i);
            }
        }
    }
    __syncthreads();
    int m = s_m; if (m > SORTW) m = SORTW;
    int n = 512; while (n < m) n <<= 1;

    unsigned long long v = (tid < n) ? cand[tid] : 0ULL;

    for (int k = 2; k <= n; k <<= 1) {
        for (int j = k >> 1; j > 0; j >>= 1) {
            bool keep_max = (((tid & j) == 0) == ((tid & k) == 0));
            unsigned long long o;
            if (j < 32) {
                o = __shfl_xor_sync(0xffffffffu, v, j);
            } else {
                cand[tid] = v;
                __syncthreads();
                o = cand[tid ^ j];
                __syncthreads();
            }
            unsigned long long mx = (v > o) ? v : o;
            unsigned long long mn = (v > o) ? o : v;
            v = keep_max ? mx : mn;
        }
    }

    if (tid < NMS_MAX) {
        float s = fkey_inv((unsigned int)(v >> 32));
        unsigned int idx = ~(unsigned int)(v & 0xffffffffu);
        if (idx >= NBOX) idx = 0;
        g_sc[b][tid] = s;
        g_sidx[b][tid] = (int)idx;
        const float* r = y + ((size_t)b * NBOX + idx) * NCH;
        float l0 = r[2], l1 = r[3], l2 = r[4], l3 = r[5];
        float dcx = r[14], dcy = r[15], dw = r[16], dh = r[17];
        float v0 = r[18], v1 = r[19], v2 = r[20], v3 = r[21];
        float cx = l0 * v0 * dw + dcx;
        float cy = l1 * v1 * dh + dcy;
        float w  = expf(l2 * v2) * dw;
        float h  = expf(l3 * v3) * dh;
        g_bx[b][tid*4+0] = (cx - w * 0.5f) * 384.0f;
        g_bx[b][tid*4+1] = (cy - h * 0.5f) * 384.0f;
        g_bx[b][tid*4+2] = (cx + w * 0.5f) * 384.0f;
        g_bx[b][tid*4+3] = (cy + h * 0.5f) * 384.0f;
    }
}

// ============ L3: IoU masks — 2 words per thread, broadcast j-loop ===========
#define ROWS_HALF 200
__global__ __launch_bounds__(256, 6) void k_iou() {
    __shared__ __align__(16) float4 bxs4[NMS_MAX];
    int wp = blockIdx.x, half = blockIdx.y, b = blockIdx.z;
    int tid = threadIdx.x;
    const float4* src = (const float4*)g_bx[b];
    for (int i = tid; i < NMS_MAX; i += 256) bxs4[i] = src[i];
    __syncthreads();

    if (tid >= ROWS_HALF) return;
    int i = half * ROWS_HALF + tid;
    float4 A = bxs4[i];
    float areai = (A.z - A.x) * (A.w - A.y);

#pragma unroll
    for (int ww = 0; ww < 2; ++ww) {
        int w = wp + ww * NWPAIR;
        if (w >= 25) {
            g_ov16[b][i * NW16 + w] = 0;
            continue;
        }
        int j0 = w * 16;
        unsigned int m = 0;
#pragma unroll 4
        for (int jj = 0; jj < 16; ++jj) {
            float4 B = bxs4[j0 + jj];
            float lt0 = fmaxf(A.x, B.x), lt1 = fmaxf(A.y, B.y);
            float rb0 = fminf(A.z, B.z), rb1 = fminf(A.w, B.w);
            float w0 = fmaxf(rb0 - lt0, 0.0f);
            float w1 = fmaxf(rb1 - lt1, 0.0f);
            float inter = w0 * w1;
            float areaj = (B.z - B.x) * (B.w - B.y);
            float uni = areai + areaj - inter;
            if (inter / fmaxf(uni, 1e-8f) > 0.45f) m |= (1u << jj);
        }
        g_ov16[b][i * NW16 + w] = (unsigned short)m;
    }
}

// ============ L4: early-exit warp greedy + selection + output ================
__global__ __launch_bounds__(512, 1)
void k_greedy(const float* __restrict__ y, float* __restrict__ out) {
    __shared__ unsigned long long keepw[MASKW];
    __shared__ int sel[NUM_PRED], selk[NUM_PRED];
    __shared__ int pp[MASKW + 1];

    int b = blockIdx.x, tid = threadIdx.x;
    if (tid < MASKW) keepw[tid] = 0ULL;
    __syncthreads();

    if (tid < 32) {
        int t = tid;
        const unsigned long long* ov = (const unsigned long long*)g_ov16[b];
        unsigned long long kw[MASKW] = {0, 0, 0, 0, 0, 0, 0};
        int cnt = 0;
#pragma unroll
        for (int blk = 0; blk < MASKW; ++blk) {
            int ilo = blk * 64 + t;
            int ihi = ilo + 32;
            unsigned long long rlo[MASKW], rhi[MASKW];
            float slo = 0.0f, shi = 0.0f;
#pragma unroll
            for (int w = 0; w < MASKW; ++w) { rlo[w] = 0ULL; rhi[w] = 0ULL; }
            if (ilo < NMS_MAX) {
#pragma unroll
                for (int w = 0; w < MASKW; ++w) rlo[w] = ov[ilo * MASKW + w];
                slo = g_sc[b][ilo];
            }
            if (ihi < NMS_MAX) {
#pragma unroll
                for (int w = 0; w < MASKW; ++w) rhi[w] = ov[ihi * MASKW + w];
                shi = g_sc[b][ihi];
            }
            unsigned long long hlo = 0ULL, hhi = 0ULL;
#pragma unroll
            for (int w = 0; w < MASKW; ++w) {
                hlo |= rlo[w] & kw[w];
                hhi |= rhi[w] & kw[w];
            }
            bool oklo = (ilo < NMS_MAX) && (slo > 0.01f) && (hlo == 0ULL);
            bool okhi = (ihi < NMS_MAX) && (shi > 0.01f) && (hhi == 0ULL);
            unsigned blo = __ballot_sync(0xffffffffu, oklo);
            unsigned bhi = __ballot_sync(0xffffffffu, okhi);
            unsigned long long K = (unsigned long long)blo |
                                   ((unsigned long long)bhi << 32);
            unsigned long long Mlo = rlo[blk] & below_mask(t);
            unsigned long long Mhi = rhi[blk] & below_mask(t + 32);
            while (true) {
                bool badlo = ((K >> t) & 1ULL) && (Mlo & K);
                bool badhi = ((K >> (t + 32)) & 1ULL) && (Mhi & K);
                unsigned bl = __ballot_sync(0xffffffffu, badlo);
                unsigned bh = __ballot_sync(0xffffffffu, badhi);
                unsigned long long bad = (unsigned long long)bl |
                                         ((unsigned long long)bh << 32);
                if (!bad) break;
                K &= ~(bad & (0ULL - bad));
            }
            kw[blk] = K;
            cnt += __popcll(K);                 // uniform across lanes
            if (cnt >= NUM_PRED) break;          // exact: fillers unreachable
        }
        if (t < MASKW) keepw[t] = kw[t];
        if (t == 0) {
            pp[0] = 0;
#pragma unroll
            for (int w = 0; w < MASKW; ++w) pp[w + 1] = pp[w] + __popcll(kw[w]);
        }
    }
    __syncthreads();

    if (tid < NMS_MAX) {
        int w = tid >> 6, bit = tid & 63;
        unsigned long long below = keepw[w] & below_mask(bit);
        int keptBefore = pp[w] + __popcll(below);
        bool kept = (keepw[w] >> bit) & 1ULL;
        int K = pp[MASKW];
        if (kept) {
            if (keptBefore < NUM_PRED) { sel[keptBefore] = tid; selk[keptBefore] = 1; }
        } else {
            int r = K + (tid - keptBefore);
            if (r < NUM_PRED) { sel[r] = tid; selk[r] = 0; }
        }
    }
    __syncthreads();

    if (tid < NUM_PRED) {
        int i = sel[tid];
        float* o = out + ((size_t)b * NUM_PRED + tid) * 13;
        o[0] = selk[tid] ? g_sc[b][i] : -1.0f;
        o[1] = g_bx[b][i*4+0]; o[2] = g_bx[b][i*4+1];
        o[3] = g_bx[b][i*4+2]; o[4] = g_bx[b][i*4+3];
        const float* r = y + ((size_t)b * NBOX + g_sidx[b][i]) * NCH;
        float dcx = r[14], dcy = r[15], dw = r[16], dh = r[17];
        float v0 = r[18], v1 = r[19];
        float dqx[4] = {dcx - dw*0.5f, dcx + dw*0.5f, dcx + dw*0.5f, dcx - dw*0.5f};
        float dqy[4] = {dcy - dh*0.5f, dcy - dh*0.5f, dcy + dh*0.5f, dcy + dh*0.5f};
#pragma unroll
        for (int k = 0; k < 4; ++k) {
            float qx = dqx[k] + r[6 + 2*k] * v0 * dw;
            float qy = dqy[k] + r[7 + 2*k] * v1 * dh;
            o[5 + 2*k]     = qx * 384.0f;
            o[5 + 2*k + 1] = qy * 384.0f;
        }
    }
}

// ---------------- launch ---------------------------------------------------
extern "C" void kernel_launch(void* const* d_in, const int* in_sizes, int n_in,
                              void* d_out, int out_size) {
    const float* y = (const float*)d_in[0];
    float* out = (float*)d_out;
    k_extract<<<dim3(HBLK, BATCH), 256>>>(y);
    k_sortdecode<<<BATCH, 1024>>>(y);
    k_iou<<<dim3(NWPAIR, 2, BATCH), 256>>>();
    k_greedy<<<BATCH, 512>>>(y, out);
}

// round 14
// speedup vs baseline: 1.1843x; 1.1175x over previous
#include <cuda_runtime.h>
#include <math.h>

#define BATCH    16
#define NBOX     120000
#define NCH      22
#define NMS_MAX  400
#define NUM_PRED 10
#define BINS     1024
#define HBLK     64
#define CAP0     4096
#define THR0     0.984375f
#define SORTW    1024
#define MASKW    7
#define NTILE    (NBOX / 2)

// ---------------- scratch ----------------------------------------------------
__device__ int                g_cc[BATCH];     // zero-init; extract last block resets
__device__ int                g_done[BATCH];
__device__ int                g_m[BATCH];
__device__ int                g_fast[BATCH];
__device__ unsigned long long g_cand0[BATCH][CAP0];
__device__ float              g_sc[BATCH][NMS_MAX];
__device__ int                g_sidx[BATCH][NMS_MAX];
__device__ __align__(16) float g_bx[BATCH][NMS_MAX * 4];

__device__ __forceinline__ unsigned int fkey(float f) {
    unsigned int u = __float_as_uint(f);
    return (u & 0x80000000u) ? ~u : (u | 0x80000000u);
}
__device__ __forceinline__ float fkey_inv(unsigned int k) {
    unsigned int u = (k & 0x80000000u) ? (k & 0x7fffffffu) : ~k;
    return __uint_as_float(u);
}
__device__ __forceinline__ int binf(float s) {     // fine bins over [THR0,1)
    int b = (int)((s - THR0) * 65536.0f);
    if (b < 0) b = 0;
    if (b > BINS - 1) b = BINS - 1;
    return b;
}
__device__ __forceinline__ int binc(float s) {     // coarse bins (fallback)
    int b = (int)(s * (float)BINS);
    if (b < 0) b = 0;
    if (b > BINS - 1) b = BINS - 1;
    return b;
}
__device__ __forceinline__ unsigned long long below_mask(int x) {
    return (x == 0) ? 0ULL : ((~0ULL) >> (64 - x));
}
__device__ __forceinline__ unsigned long long mkkey(float s, unsigned int idx) {
    return ((unsigned long long)fkey(s) << 32) | (unsigned long long)(~idx);
}

// ============ L1: strided threshold collect + fused flags ====================
__global__ void k_extract(const float* __restrict__ y) {
    int b = blockIdx.y;
    const float4* base4 = (const float4*)(y + (size_t)b * NBOX * NCH);
    int stride = gridDim.x * blockDim.x;
    int t = blockIdx.x * blockDim.x + threadIdx.x;
    for (; t + stride < NTILE; t += 2 * stride) {
        int t2 = t + stride;
        float4 a0 = __ldcs(&base4[11 * t]);
        float4 c0 = __ldcs(&base4[11 * t + 5]);
        float4 a1 = __ldcs(&base4[11 * t2]);
        float4 c1 = __ldcs(&base4[11 * t2 + 5]);
        float s00 = a0.y, s01 = c0.w, s10 = a1.y, s11 = c1.w;
        if (s00 >= THR0) {
            int p = atomicAdd(&g_cc[b], 1);
            if (p < CAP0) g_cand0[b][p] = mkkey(s00, (unsigned int)(2 * t));
        }
        if (s01 >= THR0) {
            int p = atomicAdd(&g_cc[b], 1);
            if (p < CAP0) g_cand0[b][p] = mkkey(s01, (unsigned int)(2 * t + 1));
        }
        if (s10 >= THR0) {
            int p = atomicAdd(&g_cc[b], 1);
            if (p < CAP0) g_cand0[b][p] = mkkey(s10, (unsigned int)(2 * t2));
        }
        if (s11 >= THR0) {
            int p = atomicAdd(&g_cc[b], 1);
            if (p < CAP0) g_cand0[b][p] = mkkey(s11, (unsigned int)(2 * t2 + 1));
        }
    }
    if (t < NTILE) {
        float4 a = __ldcs(&base4[11 * t]);
        float4 c = __ldcs(&base4[11 * t + 5]);
        float s0 = a.y, s1 = c.w;
        if (s0 >= THR0) {
            int p = atomicAdd(&g_cc[b], 1);
            if (p < CAP0) g_cand0[b][p] = mkkey(s0, (unsigned int)(2 * t));
        }
        if (s1 >= THR0) {
            int p = atomicAdd(&g_cc[b], 1);
            if (p < CAP0) g_cand0[b][p] = mkkey(s1, (unsigned int)(2 * t + 1));
        }
    }

    __syncthreads();
    if (threadIdx.x == 0) {
        __threadfence();
        int old = atomicAdd(&g_done[b], 1);
        if (old == gridDim.x - 1) {
            __threadfence();
            int cc = g_cc[b];
            g_m[b]    = (cc < CAP0) ? cc : CAP0;
            g_fast[b] = (cc >= NMS_MAX && cc <= CAP0) ? 1 : 0;
            g_cc[b]   = 0;
            g_done[b] = 0;
        }
    }
}

// ============ L2: candidate hist + cutoff + filter + sort + decode ===========
__global__ __launch_bounds__(1024, 1)
void k_sortdecode(const float* __restrict__ y) {
    __shared__ __align__(16) unsigned long long cand[SORTW];
    __shared__ unsigned int hist[BINS];
    __shared__ int s_m, s_cut;
    int b = blockIdx.x, tid = threadIdx.x, lane = tid & 31;
    int fast = g_fast[b];
    int cc = g_m[b];

    if (tid == 0) s_m = 0;
    cand[tid] = 0ULL;
    hist[tid] = 0u;
    __syncthreads();

    if (fast) {
        for (int i = tid; i < cc; i += 1024) {
            float s = fkey_inv((unsigned int)(g_cand0[b][i] >> 32));
            atomicAdd(&hist[binf(s)], 1u);
        }
    } else {
        const float* base = y + (size_t)b * NBOX * NCH + 1;
        for (int i = tid; i < NBOX; i += 1024) {
            float s = base[(size_t)i * NCH];
            atomicAdd(&hist[binc(s)], 1u);
        }
    }
    __syncthreads();

    if (tid < 32) {
        int cum = 0, cut = 0;
        for (int base = BINS - 32; base >= 0; base -= 32) {
            int p = (int)hist[base + 31 - lane];
#pragma unroll
            for (int o = 1; o < 32; o <<= 1) {
                int t = __shfl_up_sync(0xffffffffu, p, o);
                if (lane >= o) p += t;
            }
            unsigned ball = __ballot_sync(0xffffffffu, cum + p >= NMS_MAX);
            if (ball) { cut = base + 31 - (__ffs(ball) - 1); break; }
            cum += __shfl_sync(0xffffffffu, p, 31);
        }
        if (lane == 0) s_cut = cut;
    }
    __syncthreads();
    int cut = s_cut;

    if (fast) {
        for (int i = tid; i < cc; i += 1024) {
            unsigned long long k = g_cand0[b][i];
            float s = fkey_inv((unsigned int)(k >> 32));
            if (binf(s) >= cut) {
                int p = atomicAdd(&s_m, 1);
                if (p < SORTW) cand[p] = k;
            }
        }
    } else {
        const float* base = y + (size_t)b * NBOX * NCH + 1;
        for (int i = tid; i < NBOX; i += 1024) {
            float s = base[(size_t)i * NCH];
            if (binc(s) >= cut) {
                int p = atomicAdd(&s_m, 1);
                if (p < SORTW) cand[p] = mkkey(s, (unsigned int)i);
            }
        }
    }
    __syncthreads();
    int m = s_m; if (m > SORTW) m = SORTW;
    int n = 512; while (n < m) n <<= 1;

    unsigned long long v = (tid < n) ? cand[tid] : 0ULL;

    for (int k = 2; k <= n; k <<= 1) {
        for (int j = k >> 1; j > 0; j >>= 1) {
            bool keep_max = (((tid & j) == 0) == ((tid & k) == 0));
            unsigned long long o;
            if (j < 32) {
                o = __shfl_xor_sync(0xffffffffu, v, j);
            } else {
                cand[tid] = v;
                __syncthreads();
                o = cand[tid ^ j];
                __syncthreads();
            }
            unsigned long long mx = (v > o) ? v : o;
            unsigned long long mn = (v > o) ? o : v;
            v = keep_max ? mx : mn;
        }
    }

    if (tid < NMS_MAX) {
        float s = fkey_inv((unsigned int)(v >> 32));
        unsigned int idx = ~(unsigned int)(v & 0xffffffffu);
        if (idx >= NBOX) idx = 0;
        g_sc[b][tid] = s;
        g_sidx[b][tid] = (int)idx;
        const float* r = y + ((size_t)b * NBOX + idx) * NCH;
        float l0 = r[2], l1 = r[3], l2 = r[4], l3 = r[5];
        float dcx = r[14], dcy = r[15], dw = r[16], dh = r[17];
        float v0 = r[18], v1 = r[19], v2 = r[20], v3 = r[21];
        float cx = l0 * v0 * dw + dcx;
        float cy = l1 * v1 * dh + dcy;
        float w  = expf(l2 * v2) * dw;
        float h  = expf(l3 * v3) * dh;
        g_bx[b][tid*4+0] = (cx - w * 0.5f) * 384.0f;
        g_bx[b][tid*4+1] = (cy - h * 0.5f) * 384.0f;
        g_bx[b][tid*4+2] = (cx + w * 0.5f) * 384.0f;
        g_bx[b][tid*4+3] = (cy + h * 0.5f) * 384.0f;
    }
}

// ============ L3: fused lazy-IoU + early-exit greedy + output ================
// Per 64-row greedy block blk, only mask words 0..blk are needed (keepw[w>blk]=0).
// Compute them on demand into shared (u16 jobs, unroll-16), then warp-0 greedy.
__global__ __launch_bounds__(512, 1)
void k_nms(const float* __restrict__ y, float* __restrict__ out) {
    __shared__ __align__(16) float4 bxs4[NMS_MAX];
    __shared__ float scs[NMS_MAX];
    __shared__ __align__(8) unsigned short ovb16[64 * 28];  // cur block rows
    __shared__ unsigned long long keepw[MASKW];
    __shared__ int sel[NUM_PRED], selk[NUM_PRED];
    __shared__ int pp[MASKW + 1];
    __shared__ int s_stop, s_cnt;

    int b = blockIdx.x, tid = threadIdx.x;
    const float4* src = (const float4*)g_bx[b];
    for (int i = tid; i < NMS_MAX; i += 512) { bxs4[i] = src[i]; scs[i] = g_sc[b][i]; }
    if (tid < MASKW) keepw[tid] = 0ULL;
    if (tid == 0) { s_stop = 0; s_cnt = 0; }
    __syncthreads();

    for (int blk = 0; blk < MASKW; ++blk) {
        int rbase = blk * 64;
        int nrows = NMS_MAX - rbase; if (nrows > 64) nrows = 64;
        int nw16  = (blk + 1) * 4;                   // u16 words 0..nw16-1
        int pairs = nrows * nw16;

        // --- lazy mask build for this block's rows, words 0..blk ---
        for (int p = tid; p < pairs; p += 512) {
            int r   = p / nw16;
            int w16 = p - r * nw16;
            int j0  = w16 * 16;
            unsigned int m = 0;
            if (j0 < NMS_MAX) {
                float4 A = bxs4[rbase + r];
                float areai = (A.z - A.x) * (A.w - A.y);
#pragma unroll 4
                for (int jj = 0; jj < 16; ++jj) {
                    int j = j0 + jj;
                    if (j < NMS_MAX) {
                        float4 B = bxs4[j];
                        float lt0 = fmaxf(A.x, B.x), lt1 = fmaxf(A.y, B.y);
                        float rb0 = fminf(A.z, B.z), rb1 = fminf(A.w, B.w);
                        float w0 = fmaxf(rb0 - lt0, 0.0f);
                        float w1 = fmaxf(rb1 - lt1, 0.0f);
                        float inter = w0 * w1;
                        float areaj = (B.z - B.x) * (B.w - B.y);
                        float uni = areai + areaj - inter;
                        if (inter / fmaxf(uni, 1e-8f) > 0.45f) m |= (1u << jj);
                    }
                }
            }
            ovb16[r * 28 + w16] = (unsigned short)m;
        }
        __syncthreads();

        // --- greedy on this block (warp 0, shared masks) ---
        if (tid < 32) {
            int t = tid;
            const unsigned long long* ovr = (const unsigned long long*)ovb16;
            unsigned long long rlo[MASKW], rhi[MASKW];
            float slo = 0.0f, shi = 0.0f;
            int ilo = rbase + t, ihi = ilo + 32;
#pragma unroll
            for (int w = 0; w < MASKW; ++w) {
                // words > blk hold stale data but keepw[w>blk]==0 masks them;
                // word blk (used raw below) is freshly computed.
                rlo[w] = (t < nrows)      ? ovr[t * 7 + w]        : 0ULL;
                rhi[w] = (t + 32 < nrows) ? ovr[(t + 32) * 7 + w] : 0ULL;
            }
            if (ilo < NMS_MAX) slo = scs[ilo];
            if (ihi < NMS_MAX) shi = scs[ihi];
            unsigned long long hlo = 0ULL, hhi = 0ULL;
#pragma unroll
            for (int w = 0; w < MASKW; ++w) {
                hlo |= rlo[w] & keepw[w];
                hhi |= rhi[w] & keepw[w];
            }
            bool oklo = (ilo < NMS_MAX) && (slo > 0.01f) && (hlo == 0ULL);
            bool okhi = (ihi < NMS_MAX) && (shi > 0.01f) && (hhi == 0ULL);
            unsigned blo = __ballot_sync(0xffffffffu, oklo);
            unsigned bhi = __ballot_sync(0xffffffffu, okhi);
            unsigned long long K = (unsigned long long)blo |
                                   ((unsigned long long)bhi << 32);
            unsigned long long Mlo = rlo[blk] & below_mask(t);
            unsigned long long Mhi = rhi[blk] & below_mask(t + 32);
            while (true) {
                bool badlo = ((K >> t) & 1ULL) && (Mlo & K);
                bool badhi = ((K >> (t + 32)) & 1ULL) && (Mhi & K);
                unsigned bl = __ballot_sync(0xffffffffu, badlo);
                unsigned bh = __ballot_sync(0xffffffffu, badhi);
                unsigned long long bad = (unsigned long long)bl |
                                         ((unsigned long long)bh << 32);
                if (!bad) break;
                K &= ~(bad & (0ULL - bad));
            }
            if (t == 0) {
                keepw[blk] = K;                    // K uniform across lanes
                s_cnt += __popcll(K);
                if (s_cnt >= NUM_PRED) s_stop = 1; // exact: fillers unreachable
            }
        }
        __syncthreads();
        if (s_stop) break;
    }

    // --- prefix counts + parallel selection ---
    if (tid == 0) {
        pp[0] = 0;
#pragma unroll
        for (int w = 0; w < MASKW; ++w) pp[w + 1] = pp[w] + __popcll(keepw[w]);
    }
    __syncthreads();

    if (tid < NMS_MAX) {
        int w = tid >> 6, bit = tid & 63;
        unsigned long long below = keepw[w] & below_mask(bit);
        int keptBefore = pp[w] + __popcll(below);
        bool kept = (keepw[w] >> bit) & 1ULL;
        int K = pp[MASKW];
        if (kept) {
            if (keptBefore < NUM_PRED) { sel[keptBefore] = tid; selk[keptBefore] = 1; }
        } else {
            int r = K + (tid - keptBefore);
            if (r < NUM_PRED) { sel[r] = tid; selk[r] = 0; }
        }
    }
    __syncthreads();

    if (tid < NUM_PRED) {
        int i = sel[tid];
        float* o = out + ((size_t)b * NUM_PRED + tid) * 13;
        float4 A = bxs4[i];
        o[0] = selk[tid] ? scs[i] : -1.0f;
        o[1] = A.x; o[2] = A.y; o[3] = A.z; o[4] = A.w;
        const float* r = y + ((size_t)b * NBOX + g_sidx[b][i]) * NCH;
        float dcx = r[14], dcy = r[15], dw = r[16], dh = r[17];
        float v0 = r[18], v1 = r[19];
        float dqx[4] = {dcx - dw*0.5f, dcx + dw*0.5f, dcx + dw*0.5f, dcx - dw*0.5f};
        float dqy[4] = {dcy - dh*0.5f, dcy - dh*0.5f, dcy + dh*0.5f, dcy + dh*0.5f};
#pragma unroll
        for (int k = 0; k < 4; ++k) {
            float qx = dqx[k] + r[6 + 2*k] * v0 * dw;
            float qy = dqy[k] + r[7 + 2*k] * v1 * dh;
            o[5 + 2*k]     = qx * 384.0f;
            o[5 + 2*k + 1] = qy * 384.0f;
        }
    }
}

// ---------------- launch ---------------------------------------------------
extern "C" void kernel_launch(void* const* d_in, const int* in_sizes, int n_in,
                              void* d_out, int out_size) {
    const float* y = (const float*)d_in[0];
    float* out = (float*)d_out;
    k_extract<<<dim3(HBLK, BATCH), 256>>>(y);
    k_sortdecode<<<BATCH, 1024>>>(y);
    k_nms<<<BATCH, 512>>>(y, out);
}